// round 2
// baseline (speedup 1.0000x reference)
#include <cuda_runtime.h>

// ---------------------------------------------------------------------------
// MSELoss: out[0] = mean((yhat - y)^2) over 16384 x 4096 fp32 (512 MiB read).
// Single-kernel deterministic reduction:
//   - 1024 CTAs (fully resident on 148 SMs), 256 threads.
//   - Each thread: batches of 4 grid-strides => 8 independent LDG.128 in
//     flight (covers 577-cyc DRAM latency).
//   - Block partial -> g_partials[blockIdx.x]; last block to finish reduces
//     all partials in a FIXED order (deterministic) and writes out.
//   - Completion counter self-resets so the kernel is graph-replayable.
// ---------------------------------------------------------------------------

#define NBLK 1024
#define NTHR 256

__device__ float        g_partials[NBLK];
__device__ unsigned int g_done_count = 0;

__device__ __forceinline__ float block_reduce(float acc, float* warp_sums)
{
    #pragma unroll
    for (int off = 16; off > 0; off >>= 1)
        acc += __shfl_xor_sync(0xFFFFFFFFu, acc, off);

    int lane = threadIdx.x & 31;
    int wid  = threadIdx.x >> 5;
    if (lane == 0) warp_sums[wid] = acc;
    __syncthreads();

    float v = 0.0f;
    if (wid == 0) {
        v = (lane < NTHR / 32) ? warp_sums[lane] : 0.0f;
        #pragma unroll
        for (int off = 16; off > 0; off >>= 1)
            v += __shfl_xor_sync(0xFFFFFFFFu, v, off);
    }
    return v;  // valid in warp 0 lane 0
}

__global__ __launch_bounds__(NTHR) void mse_kernel(
    const float* __restrict__ yhat,
    const float* __restrict__ y,
    float* __restrict__ out,
    long long n4, float inv_n)
{
    const float4* __restrict__ a4 = reinterpret_cast<const float4*>(yhat);
    const float4* __restrict__ b4 = reinterpret_cast<const float4*>(y);

    const long long stride = (long long)NBLK * NTHR;
    long long base = (long long)blockIdx.x * NTHR + threadIdx.x;

    float acc = 0.0f;

    // Main path: batches of 4 strides -> 8 independent 128-bit loads in flight.
    long long i = base;
    for (; i + 3 * stride < n4; i += 4 * stride) {
        float4 a0 = a4[i];
        float4 a1 = a4[i + stride];
        float4 a2 = a4[i + 2 * stride];
        float4 a3 = a4[i + 3 * stride];
        float4 b0 = b4[i];
        float4 b1 = b4[i + stride];
        float4 b2 = b4[i + 2 * stride];
        float4 b3 = b4[i + 3 * stride];

        float d;
        d = a0.x - b0.x; acc = fmaf(d, d, acc);
        d = a0.y - b0.y; acc = fmaf(d, d, acc);
        d = a0.z - b0.z; acc = fmaf(d, d, acc);
        d = a0.w - b0.w; acc = fmaf(d, d, acc);
        d = a1.x - b1.x; acc = fmaf(d, d, acc);
        d = a1.y - b1.y; acc = fmaf(d, d, acc);
        d = a1.z - b1.z; acc = fmaf(d, d, acc);
        d = a1.w - b1.w; acc = fmaf(d, d, acc);
        d = a2.x - b2.x; acc = fmaf(d, d, acc);
        d = a2.y - b2.y; acc = fmaf(d, d, acc);
        d = a2.z - b2.z; acc = fmaf(d, d, acc);
        d = a2.w - b2.w; acc = fmaf(d, d, acc);
        d = a3.x - b3.x; acc = fmaf(d, d, acc);
        d = a3.y - b3.y; acc = fmaf(d, d, acc);
        d = a3.z - b3.z; acc = fmaf(d, d, acc);
        d = a3.w - b3.w; acc = fmaf(d, d, acc);
    }
    // Tail (empty when n4 % (4*NBLK*NTHR) == 0, which holds for 16384x4096)
    for (; i < n4; i += stride) {
        float4 a = a4[i];
        float4 b = b4[i];
        float d;
        d = a.x - b.x; acc = fmaf(d, d, acc);
        d = a.y - b.y; acc = fmaf(d, d, acc);
        d = a.z - b.z; acc = fmaf(d, d, acc);
        d = a.w - b.w; acc = fmaf(d, d, acc);
    }

    __shared__ float warp_sums[NTHR / 32];
    float bsum = block_reduce(acc, warp_sums);
    if (threadIdx.x == 0) g_partials[blockIdx.x] = bsum;

    // Last-block-done: publish partial, then the final block reduces all
    // partials in a fixed order (deterministic).
    __shared__ bool s_last;
    __threadfence();
    if (threadIdx.x == 0) {
        unsigned int prev = atomicAdd(&g_done_count, 1u);
        s_last = (prev == NBLK - 1);
    }
    __syncthreads();

    if (s_last) {
        // 1024 partials / 256 threads = 4 each, fixed order.
        float facc = 0.0f;
        #pragma unroll
        for (int k = 0; k < NBLK / NTHR; k++)
            facc += g_partials[threadIdx.x + k * NTHR];

        __syncthreads();  // reuse warp_sums safely
        float fsum = block_reduce(facc, warp_sums);
        if (threadIdx.x == 0) {
            out[0] = fsum * inv_n;
            g_done_count = 0;  // reset for next graph replay
        }
    }
}

extern "C" void kernel_launch(void* const* d_in, const int* in_sizes, int n_in,
                              void* d_out, int out_size)
{
    const float* yhat = (const float*)d_in[0];
    const float* y    = (const float*)d_in[1];
    float* out        = (float*)d_out;

    long long n  = (long long)in_sizes[0];  // 67108864, divisible by 4
    long long n4 = n / 4;

    mse_kernel<<<NBLK, NTHR>>>(yhat, y, out, n4, 1.0f / (float)n);
}

// round 4
// speedup vs baseline: 1.1210x; 1.1210x over previous
#include <cuda_runtime.h>

// ---------------------------------------------------------------------------
// MSELoss: out[0] = mean((yhat - y)^2) over 16384 x 4096 fp32 (512 MiB read).
// R2: R0's proven memory loop (2048 CTAs x 256 thr, plain float4 grid-stride,
// compiler-scheduled) + fused last-block-done finalization (kills the 3.9us
// second kernel). Deterministic: fixed-order partial reduction, no float
// atomics. Counter self-resets for graph replay.
// ---------------------------------------------------------------------------

#define NBLK 2048
#define NTHR 256

__device__ float        g_partials[NBLK];
__device__ unsigned int g_done_count = 0;

__device__ __forceinline__ float block_reduce(float acc, float* warp_sums)
{
    #pragma unroll
    for (int off = 16; off > 0; off >>= 1)
        acc += __shfl_xor_sync(0xFFFFFFFFu, acc, off);

    int lane = threadIdx.x & 31;
    int wid  = threadIdx.x >> 5;
    if (lane == 0) warp_sums[wid] = acc;
    __syncthreads();

    float v = 0.0f;
    if (wid == 0) {
        v = (lane < NTHR / 32) ? warp_sums[lane] : 0.0f;
        #pragma unroll
        for (int off = 16; off > 0; off >>= 1)
            v += __shfl_xor_sync(0xFFFFFFFFu, v, off);
    }
    return v;  // valid in warp 0 lane 0
}

__global__ __launch_bounds__(NTHR) void mse_kernel(
    const float* __restrict__ yhat,
    const float* __restrict__ y,
    float* __restrict__ out,
    long long n4, float inv_n)
{
    const float4* __restrict__ a4 = reinterpret_cast<const float4*>(yhat);
    const float4* __restrict__ b4 = reinterpret_cast<const float4*>(y);

    // --- R0's exact main loop: plain grid-stride, compiler-scheduled ---
    float acc = 0.0f;
    long long stride = (long long)gridDim.x * blockDim.x;
    for (long long i = (long long)blockIdx.x * blockDim.x + threadIdx.x;
         i < n4; i += stride) {
        float4 a = a4[i];
        float4 b = b4[i];
        float d0 = a.x - b.x;
        float d1 = a.y - b.y;
        float d2 = a.z - b.z;
        float d3 = a.w - b.w;
        acc = fmaf(d0, d0, acc);
        acc = fmaf(d1, d1, acc);
        acc = fmaf(d2, d2, acc);
        acc = fmaf(d3, d3, acc);
    }

    __shared__ float warp_sums[NTHR / 32];
    float bsum = block_reduce(acc, warp_sums);
    if (threadIdx.x == 0) g_partials[blockIdx.x] = bsum;

    // --- Fused finalization: last block to finish reduces all partials ---
    __shared__ bool s_last;
    __threadfence();
    if (threadIdx.x == 0) {
        unsigned int prev = atomicAdd(&g_done_count, 1u);
        s_last = (prev == NBLK - 1);
    }
    __syncthreads();

    if (s_last) {
        // 2048 partials / 256 threads = 8 each, fixed order => deterministic.
        float facc = 0.0f;
        #pragma unroll
        for (int k = 0; k < NBLK / NTHR; k++)
            facc += g_partials[threadIdx.x + k * NTHR];

        __syncthreads();  // warp_sums reuse
        float fsum = block_reduce(facc, warp_sums);
        if (threadIdx.x == 0) {
            out[0] = fsum * inv_n;
            g_done_count = 0;  // reset for next graph replay
        }
    }
}

extern "C" void kernel_launch(void* const* d_in, const int* in_sizes, int n_in,
                              void* d_out, int out_size)
{
    const float* yhat = (const float*)d_in[0];
    const float* y    = (const float*)d_in[1];
    float* out        = (float*)d_out;

    long long n  = (long long)in_sizes[0];  // 67108864, divisible by 4
    long long n4 = n / 4;

    mse_kernel<<<NBLK, NTHR>>>(yhat, y, out, n4, 1.0f / (float)n);
}